// round 3
// baseline (speedup 1.0000x reference)
#include <cuda_runtime.h>
#include <cstdint>

#define FULL 0xFFFFFFFFu
typedef unsigned long long u64;

// ---- packed f32x2 helpers (FFMA2 is PTX-only on sm_103a) ----
__device__ __forceinline__ u64 fma2(u64 a, u64 b, u64 c){
  u64 d; asm("fma.rn.f32x2 %0,%1,%2,%3;":"=l"(d):"l"(a),"l"(b),"l"(c)); return d;
}
__device__ __forceinline__ u64 mul2(u64 a, u64 b){
  u64 d; asm("mul.rn.f32x2 %0,%1,%2;":"=l"(d):"l"(a),"l"(b)); return d;
}
__device__ __forceinline__ u64 pack2(float x, float y){
  u64 d; asm("mov.b64 %0,{%1,%2};":"=l"(d):"f"(x),"f"(y)); return d;
}
__device__ __forceinline__ void unpack2(u64 a, float& x, float& y){
  asm("mov.b64 {%0,%1},%2;":"=f"(x),"=f"(y):"l"(a));
}

__device__ __forceinline__ void cpasync16(uint32_t dst, const void* src){
  asm volatile("cp.async.cg.shared.global [%0], [%1], 16;\n" :: "r"(dst), "l"(src));
}
#define CP_COMMIT() asm volatile("cp.async.commit_group;\n" ::: "memory")
#define CP_WAIT1()  asm volatile("cp.async.wait_group 1;\n" ::: "memory")

// ---- geometry ----
constexpr int VOCAB  = 8192;
constexpr int CROWS  = 128;            // vocab rows per chunk
constexpr int RS     = 68;             // row: [d0..31][pad 4][d32..63] -> conflict-free halves
constexpr int STAGE  = CROWS * RS;     // floats per K (or V) tile (8704)
constexpr int NCHUNK = VOCAB / CROWS;  // 64
constexpr int NSTAGE = 3;
constexpr int SMEM_BYTES = NSTAGE * 2 * STAGE * 4;  // 208896 B

// softmax computed in exp2 domain: fold d^-0.5 * log2(e) into q
constexpr float QSCALE = 0.18033688011112042f;   // 0.125 * log2(e)

// issue one chunk's K+V tiles into ring stage s
// row layout: element col = 4*qd + (qd>=8 ? 4 : 0)  (gap at cols 32..35)
__device__ __forceinline__ void issue_chunk(uint32_t smbase, int s,
                                            const float* kc, const float* vc, int tid){
  uint32_t kd = smbase + (uint32_t)(s * 2 * STAGE) * 4u;
  uint32_t vd = kd + (uint32_t)STAGE * 4u;
  #pragma unroll
  for (int i = 0; i < 4; i++){
    int item = tid + i * 512;
    int r  = item >> 4;                       // 0..127
    int qd = item & 15;                       // 0..15
    int col = 4 * qd + ((qd >> 3) << 2);      // +4 gap for upper half
    uint32_t off = (uint32_t)(r * RS + col) * 4u;
    cpasync16(kd + off, kc + r * 256 + qd * 4);
    cpasync16(vd + off, vc + r * 256 + qd * 4);
  }
}

__global__ __launch_bounds__(512, 1)
void battn_kernel(const float* __restrict__ qg, const float* __restrict__ kg,
                  const float* __restrict__ vg, float* __restrict__ outg)
{
  extern __shared__ float sm[];
  const int bt  = blockIdx.x;
  const int b   = bt >> 2, t = bt & 3;
  const int tid = threadIdx.x;
  const int w   = tid >> 5, ln = tid & 31;
  const int h    = ln & 15;    // head owned by this lane pair
  const int half = ln >> 4;    // d-half selector (0: d0..31, 1: d32..63)

  // ---- this lane's 32-float q slice, pre-scaled, packed f32x2 ----
  u64 q2[16];
  {
    const float* qb = qg + (((b * 16 + h) * 4 + t) << 6) + half * 32;
    #pragma unroll
    for (int i = 0; i < 16; i++){
      float2 f = *reinterpret_cast<const float2*>(qb + 2 * i);
      q2[i] = pack2(f.x * QSCALE, f.y * QSCALE);
    }
  }

  const uint32_t smbase = (uint32_t)__cvta_generic_to_shared(sm);
  const int kvbase = b * (VOCAB * 256) + t * 64;   // element offset; global row = 256 floats

  // ---- per-(warp,head) online softmax state (replicated across lane pair) ----
  const float NEG = -1e30f;
  float mval = NEG, lsum = 0.f, bestv = NEG;
  int   besti = 0;
  u64 acc2[16];            // this lane's 32-d slice, accumulated over all warp rows
  #pragma unroll
  for (int i = 0; i < 16; i++) acc2[i] = 0ull;

  issue_chunk(smbase, 0, kg + kvbase, vg + kvbase, tid); CP_COMMIT();
  issue_chunk(smbase, 1, kg + kvbase + CROWS * 256, vg + kvbase + CROWS * 256, tid); CP_COMMIT();

  const int r0  = w * 8;          // this warp's 8 rows within each chunk
  const int dof = half * 36;      // smem column offset of this lane's d-slice

  int stR = 0;                    // ring stage holding chunk c
  for (int c = 0; c < NCHUNK; c++){
    CP_WAIT1();                   // chunk c resident (this thread's parts)
    __syncthreads();              // publish peers' cp.async data; close out chunk c-1 reads
    // prefetch chunk c+2 into stage (stR+2)%3 (held chunk c-1: safe after the barrier)
    if (c + 2 < NCHUNK){
      int nst = stR + 2; if (nst >= NSTAGE) nst -= NSTAGE;
      issue_chunk(smbase, nst, kg + kvbase + (c + 2) * CROWS * 256,
                               vg + kvbase + (c + 2) * CROWS * 256, tid);
    }
    CP_COMMIT();                  // unconditional: keeps wait_group(1) exact at tail

    const float* ks = sm + stR * 2 * STAGE;
    const float* vs = ks + STAGE;

    // ---- partial dots: 8 rows x this lane's 32 d ----
    float l[8];
    #pragma unroll
    for (int j = 0; j < 8; j++){
      const ulonglong2* kp = reinterpret_cast<const ulonglong2*>(ks + (r0 + j) * RS + dof);
      u64 d0 = 0ull, d1 = 0ull;
      #pragma unroll
      for (int dq = 0; dq < 4; dq++){
        ulonglong2 ka = kp[2*dq], kb = kp[2*dq+1];
        d0 = fma2(ka.x, q2[4*dq],   d0);
        d1 = fma2(ka.y, q2[4*dq+1], d1);
        d0 = fma2(kb.x, q2[4*dq+2], d0);
        d1 = fma2(kb.y, q2[4*dq+3], d1);
      }
      float x, y, x2, y2;
      unpack2(d0, x, y); unpack2(d1, x2, y2);
      float part = (x + y) + (x2 + y2);
      l[j] = part + __shfl_xor_sync(FULL, part, 16);   // full 64-d logit (exp2 domain)
    }

    // ---- argmax tracking (strict > keeps first occurrence) ----
    int gi = c * CROWS + r0;
    #pragma unroll
    for (int j = 0; j < 8; j++)
      if (l[j] > bestv){ bestv = l[j]; besti = gi + j; }

    // ---- online softmax update (base-2) ----
    float cm = fmaxf(fmaxf(fmaxf(l[0],l[1]), fmaxf(l[2],l[3])),
                     fmaxf(fmaxf(l[4],l[5]), fmaxf(l[6],l[7])));
    float mnew = fmaxf(mval, cm);
    if (mnew > mval){
      float sc = exp2f(mval - mnew);
      lsum *= sc;
      u64 s2 = pack2(sc, sc);
      #pragma unroll
      for (int i = 0; i < 16; i++) acc2[i] = mul2(acc2[i], s2);
      mval = mnew;
    }
    float p[8];
    float ls = 0.f;
    #pragma unroll
    for (int j = 0; j < 8; j++){ p[j] = exp2f(l[j] - mval); ls += p[j]; }
    lsum += ls;

    // ---- acc += p_j * V[row j][lane's 32-d slice] ----
    #pragma unroll
    for (int j = 0; j < 8; j++){
      const ulonglong2* vp = reinterpret_cast<const ulonglong2*>(vs + (r0 + j) * RS + dof);
      u64 pj = pack2(p[j], p[j]);
      #pragma unroll
      for (int dq = 0; dq < 8; dq++){
        ulonglong2 vq = vp[dq];
        acc2[2*dq]   = fma2(pj, vq.x, acc2[2*dq]);
        acc2[2*dq+1] = fma2(pj, vq.y, acc2[2*dq+1]);
      }
    }

    if (++stR >= NSTAGE) stR = 0;
  }

  __syncthreads();   // loop done everywhere before merge scratch overwrites stages

  // ---- merge 16 per-warp partials per head (split-softmax combine, base-2) ----
  float* mgacc = sm;                         // [16w][16h][64d] = 16384 floats
  float* mgm   = sm + 16384;                 // [16w][16h]
  float* mgl   = sm + 16640;                 // [16w][16h]
  float* mgL   = sm + 16896;                 // [16h]
  float* mgbv  = sm + 16912;                 // [16w][16h]
  int*   mgbi  = (int*)(sm + 17168);         // [16w][16h]

  {
    #pragma unroll
    for (int i = 0; i < 16; i++){
      float fx, fy; unpack2(acc2[i], fx, fy);
      int base = (w * 16 + h) * 64 + half * 32 + 2 * i;
      mgacc[base]     = fx;
      mgacc[base + 1] = fy;
    }
    if (half == 0){
      mgm[w * 16 + h]  = mval;
      mgl[w * 16 + h]  = lsum;     // covers all 8 rows (state replicated in pair)
      mgbv[w * 16 + h] = bestv;
      mgbi[w * 16 + h] = besti;
    }
  }
  __syncthreads();

  if (tid < 16){
    int hh = tid;
    float M = NEG;
    #pragma unroll
    for (int ww = 0; ww < 16; ww++) M = fmaxf(M, mgm[ww * 16 + hh]);
    float L = 0.f;
    #pragma unroll
    for (int ww = 0; ww < 16; ww++){
      float cf = exp2f(mgm[ww * 16 + hh] - M);
      L += cf * mgl[ww * 16 + hh];
      mgm[ww * 16 + hh] = cf;      // overwrite with combine coefficient
    }
    mgL[hh] = L;
    // argmax merge (tie -> lowest index, matching jnp.argmax)
    float bv = NEG; int bi = 0x7FFFFFFF;
    #pragma unroll
    for (int pW = 0; pW < 16; pW++){
      float vvv = mgbv[pW * 16 + hh];
      int   iii = mgbi[pW * 16 + hh];
      if (vvv > bv || (vvv == bv && iii < bi)){ bv = vvv; bi = iii; }
    }
    outg[131072 + (b * 16 + hh) * 4 + t] = (float)bi;
  }
  __syncthreads();

  for (int o = tid; o < 1024; o += 512){
    int hh = o >> 6, d = o & 63;
    float s = 0.f;
    #pragma unroll
    for (int ww = 0; ww < 16; ww++)
      s += mgm[ww * 16 + hh] * mgacc[(ww * 16 + hh) * 64 + d];
    outg[((b * 16 + hh) * 4 + t) * 64 + d] = s / mgL[hh];
  }
}

extern "C" void kernel_launch(void* const* d_in, const int* in_sizes, int n_in,
                              void* d_out, int out_size)
{
  const float* q = (const float*)d_in[0];
  const float* k = (const float*)d_in[1];
  const float* v = (const float*)d_in[2];
  float* out = (float*)d_out;

  cudaFuncSetAttribute(battn_kernel, cudaFuncAttributeMaxDynamicSharedMemorySize, SMEM_BYTES);
  battn_kernel<<<128, 512, SMEM_BYTES>>>(q, k, v, out);
}

// round 4
// speedup vs baseline: 1.1131x; 1.1131x over previous
#include <cuda_runtime.h>
#include <cuda.h>
#include <cstdint>

#define FULL 0xFFFFFFFFu
typedef unsigned long long u64;

// ---- packed f32x2 helpers (FFMA2 is PTX-only on sm_103a) ----
__device__ __forceinline__ u64 fma2(u64 a, u64 b, u64 c){
  u64 d; asm("fma.rn.f32x2 %0,%1,%2,%3;":"=l"(d):"l"(a),"l"(b),"l"(c)); return d;
}
__device__ __forceinline__ u64 mul2(u64 a, u64 b){
  u64 d; asm("mul.rn.f32x2 %0,%1,%2;":"=l"(d):"l"(a),"l"(b)); return d;
}
__device__ __forceinline__ u64 pack2(float x, float y){
  u64 d; asm("mov.b64 %0,{%1,%2};":"=l"(d):"f"(x),"f"(y)); return d;
}
__device__ __forceinline__ void unpack2(u64 a, float& x, float& y){
  asm("mov.b64 {%0,%1},%2;":"=f"(x),"=f"(y):"l"(a));
}

// ---- mbarrier + TMA helpers ----
__device__ __forceinline__ void mbar_init(uint32_t a, uint32_t cnt){
  asm volatile("mbarrier.init.shared.b64 [%0], %1;" :: "r"(a), "r"(cnt) : "memory");
}
__device__ __forceinline__ void mbar_expect_tx(uint32_t a, uint32_t bytes){
  asm volatile("mbarrier.arrive.expect_tx.shared.b64 _, [%0], %1;" :: "r"(a), "r"(bytes) : "memory");
}
__device__ __forceinline__ void mbar_wait(uint32_t a, uint32_t parity){
  asm volatile(
    "{\n\t.reg .pred P;\n\t"
    "WL_%=:\n\t"
    "mbarrier.try_wait.parity.acquire.cta.shared::cta.b64 P, [%0], %1, 0x989680;\n\t"
    "@P bra.uni WD_%=;\n\t"
    "bra.uni WL_%=;\n\t"
    "WD_%=:\n\t}"
    :: "r"(a), "r"(parity) : "memory");
}
__device__ __forceinline__ void tma_load3d(uint32_t dst, const void* map,
                                           int x, int y, int z, uint32_t mbar){
  asm volatile(
    "cp.async.bulk.tensor.3d.shared::cta.global.tile.mbarrier::complete_tx::bytes "
    "[%0], [%1, {%2, %3, %4}], [%5];"
    :: "r"(dst), "l"(map), "r"(x), "r"(y), "r"(z), "r"(mbar) : "memory");
}

// ---- geometry ----
constexpr int VOCAB  = 8192;
constexpr int CROWS  = 128;              // vocab rows per chunk
constexpr int RS     = 64;               // floats per row (TMA-packed, no padding)
constexpr int STAGE  = CROWS * RS;       // 8192 floats = 32KB per K (or V) tile
constexpr int NCHUNK = VOCAB / CROWS;    // 64
constexpr int NSTAGE = 3;
constexpr int TILE_BYTES  = STAGE * 4;           // 32768
constexpr int CHUNK_BYTES = 2 * TILE_BYTES;      // K+V per stage = 65536
constexpr int SMEM_DATA   = NSTAGE * CHUNK_BYTES;          // 196608
constexpr int SMEM_BYTES  = SMEM_DATA + 64;                // + mbarriers

// softmax computed in exp2 domain: fold d^-0.5 * log2(e) into q
constexpr float QSCALE = 0.18033688011112042f;   // 0.125 * log2(e)

__global__ __launch_bounds__(512, 1)
void battn_kernel(const float* __restrict__ qg, float* __restrict__ outg,
                  const __grid_constant__ CUtensorMap tmk,
                  const __grid_constant__ CUtensorMap tmv)
{
  extern __shared__ float sm[];
  const int bt  = blockIdx.x;
  const int b   = bt >> 2, t = bt & 3;
  const int tid = threadIdx.x;
  const int w   = tid >> 5, ln = tid & 31;
  const int h    = ln & 15;    // head owned by this lane pair
  const int half = ln >> 4;    // d-quad parity: half0 owns 16B quads 0,2,..14; half1 odd

  const uint32_t smbase = (uint32_t)__cvta_generic_to_shared(sm);
  const uint32_t mbar0  = smbase + SMEM_DATA;

  // ---- this lane's 32-float q slice (interleaved quads), pre-scaled, f32x2 ----
  u64 q2[16];
  {
    const float* qb = qg + (((b * 16 + h) * 4 + t) << 6);
    #pragma unroll
    for (int j = 0; j < 8; j++){
      const float4 f = *reinterpret_cast<const float4*>(qb + (2 * j + half) * 4);
      q2[2*j]   = pack2(f.x * QSCALE, f.y * QSCALE);
      q2[2*j+1] = pack2(f.z * QSCALE, f.w * QSCALE);
    }
  }

  // ---- init mbarriers, kick off first two chunks ----
  if (tid == 0){
    #pragma unroll
    for (int s = 0; s < NSTAGE; s++) mbar_init(mbar0 + 8 * s, 1);
  }
  __syncthreads();

  const int zbase = b * VOCAB;     // dim2 coordinate base (v rows for this b)
  if (tid == 0){
    #pragma unroll
    for (int c0 = 0; c0 < 2; c0++){
      uint32_t mb = mbar0 + 8 * c0;
      uint32_t dst = smbase + c0 * CHUNK_BYTES;
      mbar_expect_tx(mb, CHUNK_BYTES);
      tma_load3d(dst,              &tmk, 0, t, zbase + c0 * CROWS, mb);
      tma_load3d(dst + TILE_BYTES, &tmv, 0, t, zbase + c0 * CROWS, mb);
    }
  }

  // ---- per-(warp,head) online softmax state (replicated across lane pair) ----
  const float NEG = -1e30f;
  float mval = NEG, lsum = 0.f, bestv = NEG;
  int   besti = 0;
  u64 acc2[16];            // this lane's 32 d-values (8 interleaved quads)
  #pragma unroll
  for (int i = 0; i < 16; i++) acc2[i] = 0ull;

  const int r0 = w * 8;    // this warp's 8 rows within each chunk
  int stR = 0;

  for (int c = 0; c < NCHUNK; c++){
    mbar_wait(mbar0 + 8 * stR, (c / 3) & 1);   // chunk c resident
    __syncthreads();                           // all warps done reading chunk c-1's stage
    if (tid == 0 && c + 2 < NCHUNK){
      int nst = stR + 2; if (nst >= NSTAGE) nst -= NSTAGE;
      uint32_t mb = mbar0 + 8 * nst;
      uint32_t dst = smbase + nst * CHUNK_BYTES;
      mbar_expect_tx(mb, CHUNK_BYTES);
      tma_load3d(dst,              &tmk, 0, t, zbase + (c + 2) * CROWS, mb);
      tma_load3d(dst + TILE_BYTES, &tmv, 0, t, zbase + (c + 2) * CROWS, mb);
    }

    const float* ks = sm + stR * (2 * STAGE);
    const float* vs = ks + STAGE;

    // ---- partial dots: 8 rows x this lane's 32 d (interleaved quads) ----
    float l[8];
    #pragma unroll
    for (int j = 0; j < 8; j++){
      const float* kr = ks + (r0 + j) * RS + half * 4;   // quad stride = 8 floats
      u64 d0 = 0ull, d1 = 0ull;
      #pragma unroll
      for (int jj = 0; jj < 8; jj++){
        ulonglong2 kq = *reinterpret_cast<const ulonglong2*>(kr + jj * 8);
        d0 = fma2(kq.x, q2[2*jj],   d0);
        d1 = fma2(kq.y, q2[2*jj+1], d1);
      }
      float x, y, x2, y2;
      unpack2(d0, x, y); unpack2(d1, x2, y2);
      float part = (x + y) + (x2 + y2);
      l[j] = part + __shfl_xor_sync(FULL, part, 16);   // full 64-d logit (exp2 domain)
    }

    // ---- argmax tracking (strict > keeps first occurrence) ----
    int gi = c * CROWS + r0;
    #pragma unroll
    for (int j = 0; j < 8; j++)
      if (l[j] > bestv){ bestv = l[j]; besti = gi + j; }

    // ---- online softmax update (base-2) ----
    float cm = fmaxf(fmaxf(fmaxf(l[0],l[1]), fmaxf(l[2],l[3])),
                     fmaxf(fmaxf(l[4],l[5]), fmaxf(l[6],l[7])));
    float mnew = fmaxf(mval, cm);
    if (mnew > mval){
      float sc = exp2f(mval - mnew);
      lsum *= sc;
      u64 s2 = pack2(sc, sc);
      #pragma unroll
      for (int i = 0; i < 16; i++) acc2[i] = mul2(acc2[i], s2);
      mval = mnew;
    }
    float p[8];
    float ls = 0.f;
    #pragma unroll
    for (int j = 0; j < 8; j++){ p[j] = exp2f(l[j] - mval); ls += p[j]; }
    lsum += ls;

    // ---- acc += p_j * V[row j][lane's quads] ----
    #pragma unroll
    for (int j = 0; j < 8; j++){
      const float* vr = vs + (r0 + j) * RS + half * 4;
      u64 pj = pack2(p[j], p[j]);
      #pragma unroll
      for (int jj = 0; jj < 8; jj++){
        ulonglong2 vq = *reinterpret_cast<const ulonglong2*>(vr + jj * 8);
        acc2[2*jj]   = fma2(pj, vq.x, acc2[2*jj]);
        acc2[2*jj+1] = fma2(pj, vq.y, acc2[2*jj+1]);
      }
    }

    if (++stR >= NSTAGE) stR = 0;
  }

  __syncthreads();   // loop done everywhere before merge scratch overwrites stages

  // ---- merge 16 per-warp partials per head (split-softmax combine, base-2) ----
  float* mgacc = sm;                         // [16w][16h][64d] = 16384 floats
  float* mgm   = sm + 16384;                 // [16w][16h]
  float* mgl   = sm + 16640;                 // [16w][16h]
  float* mgL   = sm + 16896;                 // [16h]
  float* mgbv  = sm + 16912;                 // [16w][16h]
  int*   mgbi  = (int*)(sm + 17168);         // [16w][16h]

  {
    #pragma unroll
    for (int j = 0; j < 8; j++){
      float f0, f1, f2, f3;
      unpack2(acc2[2*j],   f0, f1);
      unpack2(acc2[2*j+1], f2, f3);
      int base = (w * 16 + h) * 64 + (2 * j + half) * 4;
      mgacc[base]     = f0;
      mgacc[base + 1] = f1;
      mgacc[base + 2] = f2;
      mgacc[base + 3] = f3;
    }
    if (half == 0){
      mgm[w * 16 + h]  = mval;
      mgl[w * 16 + h]  = lsum;     // covers all 8 rows (state replicated in pair)
      mgbv[w * 16 + h] = bestv;
      mgbi[w * 16 + h] = besti;
    }
  }
  __syncthreads();

  if (tid < 16){
    int hh = tid;
    float M = NEG;
    #pragma unroll
    for (int ww = 0; ww < 16; ww++) M = fmaxf(M, mgm[ww * 16 + hh]);
    float L = 0.f;
    #pragma unroll
    for (int ww = 0; ww < 16; ww++){
      float cf = exp2f(mgm[ww * 16 + hh] - M);
      L += cf * mgl[ww * 16 + hh];
      mgm[ww * 16 + hh] = cf;      // overwrite with combine coefficient
    }
    mgL[hh] = L;
    // argmax merge (tie -> lowest index, matching jnp.argmax)
    float bv = NEG; int bi = 0x7FFFFFFF;
    #pragma unroll
    for (int pW = 0; pW < 16; pW++){
      float vvv = mgbv[pW * 16 + hh];
      int   iii = mgbi[pW * 16 + hh];
      if (vvv > bv || (vvv == bv && iii < bi)){ bv = vvv; bi = iii; }
    }
    outg[131072 + (b * 16 + hh) * 4 + t] = (float)bi;
  }
  __syncthreads();

  for (int o = tid; o < 1024; o += 512){
    int hh = o >> 6, d = o & 63;
    float s = 0.f;
    #pragma unroll
    for (int ww = 0; ww < 16; ww++)
      s += mgm[ww * 16 + hh] * mgacc[(ww * 16 + hh) * 64 + d];
    outg[((b * 16 + hh) * 4 + t) * 64 + d] = s / mgL[hh];
  }
}

// ---- host: tensormap encode via driver entry point (no -lcuda needed) ----
typedef CUresult (*PFN_encode)(CUtensorMap*, CUtensorMapDataType, cuuint32_t, void*,
                               const cuuint64_t*, const cuuint64_t*, const cuuint32_t*,
                               const cuuint32_t*, CUtensorMapInterleave, CUtensorMapSwizzle,
                               CUtensorMapL2promotion, CUtensorMapFloatOOBfill);

static PFN_encode get_encode(){
  static PFN_encode fn = nullptr;
  if (!fn){
    void* p = nullptr;
    cudaDriverEntryPointQueryResult st;
    cudaGetDriverEntryPointByVersion("cuTensorMapEncodeTiled", &p, 12000,
                                     cudaEnableDefault, &st);
    fn = (PFN_encode)p;
  }
  return fn;
}

static void make_map(CUtensorMap* m, void* ptr){
  cuuint64_t dims[3]    = {64, 4, (cuuint64_t)32 * VOCAB};
  cuuint64_t strides[2] = {64 * 4, 4 * 64 * 4};      // bytes: t stride, vocab-row stride
  cuuint32_t box[3]     = {64, 1, CROWS};
  cuuint32_t estr[3]    = {1, 1, 1};
  get_encode()(m, CU_TENSOR_MAP_DATA_TYPE_FLOAT32, 3, ptr, dims, strides, box, estr,
               CU_TENSOR_MAP_INTERLEAVE_NONE, CU_TENSOR_MAP_SWIZZLE_NONE,
               CU_TENSOR_MAP_L2_PROMOTION_L2_128B, CU_TENSOR_MAP_FLOAT_OOB_FILL_NONE);
}

extern "C" void kernel_launch(void* const* d_in, const int* in_sizes, int n_in,
                              void* d_out, int out_size)
{
  const float* q = (const float*)d_in[0];
  float* out = (float*)d_out;

  CUtensorMap tmk, tmv;
  make_map(&tmk, (void*)d_in[1]);
  make_map(&tmv, (void*)d_in[2]);

  cudaFuncSetAttribute(battn_kernel, cudaFuncAttributeMaxDynamicSharedMemorySize, SMEM_BYTES);
  battn_kernel<<<128, 512, SMEM_BYTES>>>(q, out, tmk, tmv);
}

// round 9
// speedup vs baseline: 1.3320x; 1.1966x over previous
#include <cuda_runtime.h>
#include <cuda.h>
#include <cstdint>

#define FULL 0xFFFFFFFFu
typedef unsigned long long u64;

// ---- packed f32x2 helpers (PTX-only on sm_103a) ----
__device__ __forceinline__ u64 fma2(u64 a, u64 b, u64 c){
  u64 d; asm("fma.rn.f32x2 %0,%1,%2,%3;":"=l"(d):"l"(a),"l"(b),"l"(c)); return d;
}
__device__ __forceinline__ u64 mul2(u64 a, u64 b){
  u64 d; asm("mul.rn.f32x2 %0,%1,%2;":"=l"(d):"l"(a),"l"(b)); return d;
}
__device__ __forceinline__ u64 add2(u64 a, u64 b){
  u64 d; asm("add.rn.f32x2 %0,%1,%2;":"=l"(d):"l"(a),"l"(b)); return d;
}
__device__ __forceinline__ u64 pack2(float x, float y){
  u64 d; asm("mov.b64 %0,{%1,%2};":"=l"(d):"f"(x),"f"(y)); return d;
}
__device__ __forceinline__ void unpack2(u64 a, float& x, float& y){
  asm("mov.b64 {%0,%1},%2;":"=f"(x),"=f"(y):"l"(a));
}

// ---- mbarrier + TMA helpers ----
__device__ __forceinline__ void mbar_init(uint32_t a, uint32_t cnt){
  asm volatile("mbarrier.init.shared.b64 [%0], %1;" :: "r"(a), "r"(cnt) : "memory");
}
__device__ __forceinline__ void mbar_expect_tx(uint32_t a, uint32_t bytes){
  asm volatile("mbarrier.arrive.expect_tx.shared.b64 _, [%0], %1;" :: "r"(a), "r"(bytes) : "memory");
}
__device__ __forceinline__ void mbar_wait(uint32_t a, uint32_t parity){
  asm volatile(
    "{\n\t.reg .pred P;\n\t"
    "WL_%=:\n\t"
    "mbarrier.try_wait.parity.acquire.cta.shared::cta.b64 P, [%0], %1, 0x989680;\n\t"
    "@P bra.uni WD_%=;\n\t"
    "bra.uni WL_%=;\n\t"
    "WD_%=:\n\t}"
    :: "r"(a), "r"(parity) : "memory");
}
__device__ __forceinline__ void tma_load3d(uint32_t dst, const void* map,
                                           int x, int y, int z, uint32_t mbar){
  asm volatile(
    "cp.async.bulk.tensor.3d.shared::cta.global.tile.mbarrier::complete_tx::bytes "
    "[%0], [%1, {%2, %3, %4}], [%5];"
    :: "r"(dst), "l"(map), "r"(x), "r"(y), "r"(z), "r"(mbar) : "memory");
}

// ---- geometry ----
constexpr int VOCAB  = 8192;
constexpr int CROWS  = 128;              // vocab rows per chunk
constexpr int RS     = 64;               // floats per row (TMA-packed)
constexpr int STAGE  = CROWS * RS;       // 8192 floats = 32KB per K (or V) tile
constexpr int NCHUNK = VOCAB / CROWS;    // 64
constexpr int NSTAGE = 3;
constexpr int TILE_BYTES  = STAGE * 4;           // 32768
constexpr int CHUNK_BYTES = 2 * TILE_BYTES;      // K+V per stage = 65536
constexpr int SMEM_DATA   = NSTAGE * CHUNK_BYTES;          // 196608
constexpr int SMEM_BYTES  = SMEM_DATA + 64;

// softmax computed in exp2 domain: fold d^-0.5 * log2(e) into q
constexpr float QSCALE = 0.18033688011112042f;   // 0.125 * log2(e)

__global__ __launch_bounds__(512, 1)
void battn_kernel(const float* __restrict__ qg, float* __restrict__ outg,
                  const __grid_constant__ CUtensorMap tmk,
                  const __grid_constant__ CUtensorMap tmv)
{
  extern __shared__ float sm[];
  const int bt  = blockIdx.x;
  const int b   = bt >> 2, t = bt & 3;
  const int tid = threadIdx.x;
  const int w   = tid >> 5, ln = tid & 31;
  const int hp  = ln & 7;          // head pair: owns heads 2hp, 2hp+1
  const int qt  = ln >> 3;         // quarter lane: owns quads {jj*4+qt : jj=0..3}
  const int h0  = 2 * hp, h1 = 2 * hp + 1;

  const uint32_t smbase = (uint32_t)__cvta_generic_to_shared(sm);
  const uint32_t mbar0  = smbase + SMEM_DATA;

  // ---- q slices for both owned heads: quad jj lives at d = jj*16 + qt*4 ----
  u64 q0[8], q1[8];
  {
    const float* qa = qg + (((b * 16 + h0) * 4 + t) << 6) + qt * 4;
    const float* qb = qg + (((b * 16 + h1) * 4 + t) << 6) + qt * 4;
    #pragma unroll
    for (int jj = 0; jj < 4; jj++){
      float4 fa = *reinterpret_cast<const float4*>(qa + jj * 16);
      float4 fb = *reinterpret_cast<const float4*>(qb + jj * 16);
      q0[2*jj]   = pack2(fa.x * QSCALE, fa.y * QSCALE);
      q0[2*jj+1] = pack2(fa.z * QSCALE, fa.w * QSCALE);
      q1[2*jj]   = pack2(fb.x * QSCALE, fb.y * QSCALE);
      q1[2*jj+1] = pack2(fb.z * QSCALE, fb.w * QSCALE);
    }
  }

  if (tid == 0){
    #pragma unroll
    for (int s = 0; s < NSTAGE; s++) mbar_init(mbar0 + 8 * s, 1);
  }
  __syncthreads();

  const int zbase = b * VOCAB;
  if (tid == 0){
    #pragma unroll
    for (int c0 = 0; c0 < 2; c0++){
      uint32_t mb = mbar0 + 8 * c0;
      uint32_t dst = smbase + c0 * CHUNK_BYTES;
      mbar_expect_tx(mb, CHUNK_BYTES);
      tma_load3d(dst,              &tmk, 0, t, zbase + c0 * CROWS, mb);
      tma_load3d(dst + TILE_BYTES, &tmv, 0, t, zbase + c0 * CROWS, mb);
    }
  }

  // ---- per-(warp,head) online softmax state (replicated across 4 qt lanes) ----
  const float NEG = -1e30f;
  float m0 = NEG, m1 = NEG, ls0 = 0.f, ls1 = 0.f;
  float bv0 = NEG, bv1 = NEG;
  int   bi0 = 0, bi1 = 0;
  u64 acc0[8], acc1[8];        // per-head accumulators; pair 2jj,2jj+1 = quad jj
  #pragma unroll
  for (int i = 0; i < 8; i++){ acc0[i] = 0ull; acc1[i] = 0ull; }

  const int r0 = w * 8;        // this warp's 8 rows within each chunk
  int stR = 0, phase = 0;      // ring stage + its mbarrier phase (flip on wrap)

  for (int c = 0; c < NCHUNK; c++){
    mbar_wait(mbar0 + 8 * stR, phase);
    __syncthreads();
    if (tid == 0 && c + 2 < NCHUNK){
      int nst = stR + 2; if (nst >= NSTAGE) nst -= NSTAGE;
      uint32_t mb = mbar0 + 8 * nst;
      uint32_t dst = smbase + nst * CHUNK_BYTES;
      mbar_expect_tx(mb, CHUNK_BYTES);
      tma_load3d(dst,              &tmk, 0, t, zbase + (c + 2) * CROWS, mb);
      tma_load3d(dst + TILE_BYTES, &tmv, 0, t, zbase + (c + 2) * CROWS, mb);
    }

    const float* ks = sm + stR * (2 * STAGE);
    const float* vs = ks + STAGE;

    // ---- K pass: 8 rows, both heads; packed logits per row ----
    // lane reads quads at row*64 + jj*16 + qt*4 : lanes contiguous within 64B -> conflict-free
    u64 lp[8];
    #pragma unroll
    for (int j = 0; j < 8; j++){
      const float* krow = ks + (r0 + j) * RS + qt * 4;
      ulonglong2 ka = *reinterpret_cast<const ulonglong2*>(krow);
      ulonglong2 kb = *reinterpret_cast<const ulonglong2*>(krow + 16);
      ulonglong2 kc = *reinterpret_cast<const ulonglong2*>(krow + 32);
      ulonglong2 kd = *reinterpret_cast<const ulonglong2*>(krow + 48);
      u64 c0a = 0ull, c0b = 0ull, c1a = 0ull, c1b = 0ull;
      c0a = fma2(ka.x, q0[0], c0a); c0b = fma2(ka.y, q0[1], c0b);
      c1a = fma2(ka.x, q1[0], c1a); c1b = fma2(ka.y, q1[1], c1b);
      c0a = fma2(kb.x, q0[2], c0a); c0b = fma2(kb.y, q0[3], c0b);
      c1a = fma2(kb.x, q1[2], c1a); c1b = fma2(kb.y, q1[3], c1b);
      c0a = fma2(kc.x, q0[4], c0a); c0b = fma2(kc.y, q0[5], c0b);
      c1a = fma2(kc.x, q1[4], c1a); c1b = fma2(kc.y, q1[5], c1b);
      c0a = fma2(kd.x, q0[6], c0a); c0b = fma2(kd.y, q0[7], c0b);
      c1a = fma2(kd.x, q1[6], c1a); c1b = fma2(kd.y, q1[7], c1b);
      u64 s0 = add2(c0a, c0b), s1 = add2(c1a, c1b);
      float x0, y0, x1, y1;
      unpack2(s0, x0, y0); unpack2(s1, x1, y1);
      u64 part = pack2(x0 + y0, x1 + y1);      // [head0 partial, head1 partial]
      part = add2(part, __shfl_xor_sync(FULL, part, 8));
      part = add2(part, __shfl_xor_sync(FULL, part, 16));
      lp[j] = part;                            // full logits for both heads
    }

    // ---- softmax + argmax per head (base-2 domain) ----
    float l0[8], l1[8];
    #pragma unroll
    for (int j = 0; j < 8; j++) unpack2(lp[j], l0[j], l1[j]);

    int gi = c * CROWS + r0;
    #pragma unroll
    for (int j = 0; j < 8; j++){
      if (l0[j] > bv0){ bv0 = l0[j]; bi0 = gi + j; }
      if (l1[j] > bv1){ bv1 = l1[j]; bi1 = gi + j; }
    }

    float cm0 = fmaxf(fmaxf(fmaxf(l0[0],l0[1]), fmaxf(l0[2],l0[3])),
                      fmaxf(fmaxf(l0[4],l0[5]), fmaxf(l0[6],l0[7])));
    float cm1 = fmaxf(fmaxf(fmaxf(l1[0],l1[1]), fmaxf(l1[2],l1[3])),
                      fmaxf(fmaxf(l1[4],l1[5]), fmaxf(l1[6],l1[7])));
    float mn0 = fmaxf(m0, cm0), mn1 = fmaxf(m1, cm1);
    if (mn0 > m0){
      float sc = exp2f(m0 - mn0); ls0 *= sc;
      u64 s2 = pack2(sc, sc);
      #pragma unroll
      for (int i = 0; i < 8; i++) acc0[i] = mul2(acc0[i], s2);
      m0 = mn0;
    }
    if (mn1 > m1){
      float sc = exp2f(m1 - mn1); ls1 *= sc;
      u64 s2 = pack2(sc, sc);
      #pragma unroll
      for (int i = 0; i < 8; i++) acc1[i] = mul2(acc1[i], s2);
      m1 = mn1;
    }
    float p0[8], p1[8];
    float a0 = 0.f, a1 = 0.f;
    #pragma unroll
    for (int j = 0; j < 8; j++){
      p0[j] = exp2f(l0[j] - m0); a0 += p0[j];
      p1[j] = exp2f(l1[j] - m1); a1 += p1[j];
    }
    ls0 += a0; ls1 += a1;

    // ---- V pass: acc_h += p_h[j] * V[row j][owned quads] ----
    #pragma unroll
    for (int j = 0; j < 8; j++){
      const float* vrow = vs + (r0 + j) * RS + qt * 4;
      ulonglong2 va = *reinterpret_cast<const ulonglong2*>(vrow);
      ulonglong2 vb = *reinterpret_cast<const ulonglong2*>(vrow + 16);
      ulonglong2 vc = *reinterpret_cast<const ulonglong2*>(vrow + 32);
      ulonglong2 vd = *reinterpret_cast<const ulonglong2*>(vrow + 48);
      u64 pj0 = pack2(p0[j], p0[j]);
      u64 pj1 = pack2(p1[j], p1[j]);
      acc0[0] = fma2(pj0, va.x, acc0[0]); acc0[1] = fma2(pj0, va.y, acc0[1]);
      acc1[0] = fma2(pj1, va.x, acc1[0]); acc1[1] = fma2(pj1, va.y, acc1[1]);
      acc0[2] = fma2(pj0, vb.x, acc0[2]); acc0[3] = fma2(pj0, vb.y, acc0[3]);
      acc1[2] = fma2(pj1, vb.x, acc1[2]); acc1[3] = fma2(pj1, vb.y, acc1[3]);
      acc0[4] = fma2(pj0, vc.x, acc0[4]); acc0[5] = fma2(pj0, vc.y, acc0[5]);
      acc1[4] = fma2(pj1, vc.x, acc1[4]); acc1[5] = fma2(pj1, vc.y, acc1[5]);
      acc0[6] = fma2(pj0, vd.x, acc0[6]); acc0[7] = fma2(pj0, vd.y, acc0[7]);
      acc1[6] = fma2(pj1, vd.x, acc1[6]); acc1[7] = fma2(pj1, vd.y, acc1[7]);
    }

    if (++stR >= NSTAGE){ stR = 0; phase ^= 1; }
  }

  __syncthreads();   // loop done everywhere before merge scratch overwrites stages

  // ---- merge 16 per-warp partials per head (split-softmax combine, base-2) ----
  float* mgacc = sm;                         // [16w][16h][64d] = 16384 floats
  float* mgm   = sm + 16384;                 // [16w][16h]
  float* mgl   = sm + 16640;                 // [16w][16h]
  float* mgL   = sm + 16896;                 // [16h]
  float* mgbv  = sm + 16912;                 // [16w][16h]
  int*   mgbi  = (int*)(sm + 17168);         // [16w][16h]

  {
    #pragma unroll
    for (int jj = 0; jj < 4; jj++){
      float f0, f1, f2, f3, g0, g1, g2, g3;
      unpack2(acc0[2*jj],   f0, f1);
      unpack2(acc0[2*jj+1], f2, f3);
      unpack2(acc1[2*jj],   g0, g1);
      unpack2(acc1[2*jj+1], g2, g3);
      int base0 = (w * 16 + h0) * 64 + jj * 16 + qt * 4;
      int base1 = (w * 16 + h1) * 64 + jj * 16 + qt * 4;
      mgacc[base0]     = f0;
      mgacc[base0 + 1] = f1;
      mgacc[base0 + 2] = f2;
      mgacc[base0 + 3] = f3;
      mgacc[base1]     = g0;
      mgacc[base1 + 1] = g1;
      mgacc[base1 + 2] = g2;
      mgacc[base1 + 3] = g3;
    }
    if (qt == 0){
      mgm[w * 16 + h0]  = m0;   mgm[w * 16 + h1]  = m1;
      mgl[w * 16 + h0]  = ls0;  mgl[w * 16 + h1]  = ls1;
      mgbv[w * 16 + h0] = bv0;  mgbv[w * 16 + h1] = bv1;
      mgbi[w * 16 + h0] = bi0;  mgbi[w * 16 + h1] = bi1;
    }
  }
  __syncthreads();

  if (tid < 16){
    int hh = tid;
    float M = NEG;
    #pragma unroll
    for (int ww = 0; ww < 16; ww++) M = fmaxf(M, mgm[ww * 16 + hh]);
    float L = 0.f;
    #pragma unroll
    for (int ww = 0; ww < 16; ww++){
      float cf = exp2f(mgm[ww * 16 + hh] - M);
      L += cf * mgl[ww * 16 + hh];
      mgm[ww * 16 + hh] = cf;
    }
    mgL[hh] = L;
    // argmax merge (tie -> lowest index, matching jnp.argmax)
    float bv = NEG; int bi = 0x7FFFFFFF;
    #pragma unroll
    for (int pW = 0; pW < 16; pW++){
      float vvv = mgbv[pW * 16 + hh];
      int   iii = mgbi[pW * 16 + hh];
      if (vvv > bv || (vvv == bv && iii < bi)){ bv = vvv; bi = iii; }
    }
    outg[131072 + (b * 16 + hh) * 4 + t] = (float)bi;
  }
  __syncthreads();

  for (int o = tid; o < 1024; o += 512){
    int hh = o >> 6, d = o & 63;
    float s = 0.f;
    #pragma unroll
    for (int ww = 0; ww < 16; ww++)
      s += mgm[ww * 16 + hh] * mgacc[(ww * 16 + hh) * 64 + d];
    outg[((b * 16 + hh) * 4 + t) * 64 + d] = s / mgL[hh];
  }
}

// ---- host: tensormap encode via driver entry point (no -lcuda needed) ----
typedef CUresult (*PFN_encode)(CUtensorMap*, CUtensorMapDataType, cuuint32_t, void*,
                               const cuuint64_t*, const cuuint64_t*, const cuuint32_t*,
                               const cuuint32_t*, CUtensorMapInterleave, CUtensorMapSwizzle,
                               CUtensorMapL2promotion, CUtensorMapFloatOOBfill);

static PFN_encode get_encode(){
  static PFN_encode fn = nullptr;
  if (!fn){
    void* p = nullptr;
    cudaDriverEntryPointQueryResult st;
    cudaGetDriverEntryPointByVersion("cuTensorMapEncodeTiled", &p, 12000,
                                     cudaEnableDefault, &st);
    fn = (PFN_encode)p;
  }
  return fn;
}

static void make_map(CUtensorMap* m, void* ptr){
  cuuint64_t dims[3]    = {64, 4, (cuuint64_t)32 * VOCAB};
  cuuint64_t strides[2] = {64 * 4, 4 * 64 * 4};
  cuuint32_t box[3]     = {64, 1, CROWS};
  cuuint32_t estr[3]    = {1, 1, 1};
  get_encode()(m, CU_TENSOR_MAP_DATA_TYPE_FLOAT32, 3, ptr, dims, strides, box, estr,
               CU_TENSOR_MAP_INTERLEAVE_NONE, CU_TENSOR_MAP_SWIZZLE_NONE,
               CU_TENSOR_MAP_L2_PROMOTION_L2_128B, CU_TENSOR_MAP_FLOAT_OOB_FILL_NONE);
}

extern "C" void kernel_launch(void* const* d_in, const int* in_sizes, int n_in,
                              void* d_out, int out_size)
{
  const float* q = (const float*)d_in[0];
  float* out = (float*)d_out;

  CUtensorMap tmk, tmv;
  make_map(&tmk, (void*)d_in[1]);
  make_map(&tmv, (void*)d_in[2]);

  cudaFuncSetAttribute(battn_kernel, cudaFuncAttributeMaxDynamicSharedMemorySize, SMEM_BYTES);
  battn_kernel<<<128, 512, SMEM_BYTES>>>(q, out, tmk, tmv);
}